// round 14
// baseline (speedup 1.0000x reference)
#include <cuda_runtime.h>
#include <stdint.h>

// ---------------------------------------------------------------------------
// TiledFeaturesMap: B=4, N=2048, C=512, FS=1, T_SZ=9, T_STEP=6, T_CUT=2
// Output: float32 [ f_ns (K) | f_tiles (K*512*81) ], K = out_size/41473.
// SINGLE fused kernel: blocks 0..3 run per-batch setup, release a device
// flag; all K*8 blocks then emit one (tile, 64-ch chunk) each. Last block
// resets the flags for graph-replay determinism.
// ---------------------------------------------------------------------------

#define NB 4
#define NP 2048
#define NC 512
#define TSZ 9
#define CELLS 81
#define TILE_ELEMS 41472
#define SLOTMAX 512
#define CHUNK 64                        // channels per block
#define NCHUNK (NC / CHUNK)             // 8
#define CHUNK_ELEMS (CHUNK * CELLS)     // 5184

__device__ int g_selcnt[NB];
__device__ int g_cnt[NB * SLOTMAX];
__device__ int g_list[NB * SLOTMAX * CELLS];   // (cell<<16)|n
__device__ int g_ready = 0;
__device__ int g_done  = 0;

// ---------------------------------------------------------------------------
// setup for one batch, 256 threads (blocks 0..3 only). Coords re-loaded per
// phase (L2-hot) to keep register pressure at the launch_bounds cap.
// ---------------------------------------------------------------------------
__device__ __forceinline__ void load_pt(const void* ys, const void* xs, bool is64,
                                        int idx, int& y, int& x)
{
    if (is64) {
        y = (int)((const long long*)ys)[idx];
        x = (int)((const long long*)xs)[idx];
    } else {
        y = ((const int*)ys)[idx];
        x = ((const int*)xs)[idx];
    }
}

__device__ void do_setup(int b, const void* __restrict__ ys_raw,
                         const void* __restrict__ xs_raw)
{
    const int tid = threadIdx.x;
    __shared__ int s_bad, s_ymin, s_ymax, s_xmin, s_xmax;
    __shared__ unsigned char s_mask[512];
    __shared__ short s_slot[512];
    __shared__ int s_cntA[512];
    __shared__ int s_ws[8];
    __shared__ int s_nH, s_nW, s_T;

    if (tid == 0) { s_bad = 0; s_ymin = 1 << 30; s_ymax = -1; s_xmin = 1 << 30; s_xmax = -1; }
    s_mask[tid] = 0;  s_mask[tid + 256] = 0;
    s_cntA[tid] = 0;  s_cntA[tid + 256] = 0;
    __syncthreads();

    // dtype detect (int64 LE: odd 32-bit words all 0)
    {
        const int* yw = (const int*)ys_raw;
        const int* xw = (const int*)xs_raw;
        int bad = 0;
        for (int i = b * 4096 + 1 + 2 * tid; i < (b + 1) * 4096; i += 512)
            bad |= yw[i] | xw[i];
        bad = __reduce_or_sync(0xffffffffu, bad);
        if ((tid & 31) == 0 && bad) atomicOr(&s_bad, 1);
    }
    __syncthreads();
    const bool is64 = (s_bad == 0);

    // phase 1: min/max
    {
        int ymn = 1 << 30, ymx = -1, xmn = 1 << 30, xmx = -1;
        for (int j = 0; j < 8; j++) {
            int y, x; load_pt(ys_raw, xs_raw, is64, b * NP + tid + j * 256, y, x);
            ymn = min(ymn, y); ymx = max(ymx, y);
            xmn = min(xmn, x); xmx = max(xmx, x);
        }
        ymn = __reduce_min_sync(0xffffffffu, ymn);
        ymx = __reduce_max_sync(0xffffffffu, ymx);
        xmn = __reduce_min_sync(0xffffffffu, xmn);
        xmx = __reduce_max_sync(0xffffffffu, xmx);
        if ((tid & 31) == 0) {
            atomicMin(&s_ymin, ymn); atomicMax(&s_ymax, ymx);
            atomicMin(&s_xmin, xmn); atomicMax(&s_xmax, xmx);
        }
    }
    __syncthreads();
    if (tid == 0) {
        s_nH = (s_ymax - s_ymin + 1) / 6 + 1;
        s_nW = (s_xmax - s_xmin + 1) / 6 + 1;
        s_T = s_nH * s_nW;
    }
    __syncthreads();
    const int nH = s_nH, nW = s_nW, T = s_T;
    const int ymin = s_ymin, xmin = s_xmin;

    // phase 2: center occupancy (r%6: 1 -> none; 0 -> tile q-1; 2..5 -> tile q)
    for (int j = 0; j < 8; j++) {
        int y, x; load_pt(ys_raw, xs_raw, is64, b * NP + tid + j * 256, y, x);
        y -= ymin; x -= xmin;
        const int qy = y / 6, ry = y - 6 * qy;
        const int qx = x / 6, rx = x - 6 * qx;
        const int cy = (ry == 1) ? -1 : ((ry == 0) ? qy - 1 : qy);
        const int cx = (rx == 1) ? -1 : ((rx == 0) ? qx - 1 : qx);
        if (cy >= 0 && cx >= 0) s_mask[cy * nW + cx] = 1;
    }
    __syncthreads();

    // inclusive scan over T (<=441) flags, 2 consecutive elements per thread
    {
        const int w = tid >> 5, lane = tid & 31;
        const int e0 = 2 * tid, e1 = 2 * tid + 1;
        const int f0 = (e0 < T) ? (int)s_mask[e0] : 0;
        const int f1 = (e1 < T) ? (int)s_mask[e1] : 0;
        const int lsum = f0 + f1;
        int v = lsum;
        for (int off = 1; off < 32; off <<= 1) {
            const int t = __shfl_up_sync(0xffffffffu, v, off);
            if (lane >= off) v += t;
        }
        if (lane == 31) s_ws[w] = v;
        __syncthreads();
        if (w == 0 && lane < 8) {
            int sv = s_ws[lane];
            for (int off = 1; off < 8; off <<= 1) {
                const int t = __shfl_up_sync(0xffu, sv, off);
                if (lane >= off) sv += t;
            }
            s_ws[lane] = sv;
        }
        __syncthreads();
        const int pre = (w > 0) ? s_ws[w - 1] : 0;
        const int excl = pre + v - lsum;            // exclusive prefix at e0
        s_slot[e0] = (short)(f0 ? excl : -1);
        s_slot[e1] = (short)(f1 ? excl + f0 : -1);
        if (tid == 0) g_selcnt[b] = s_ws[7];
    }
    __syncthreads();

    // phase 3: scatter points into per-slot lists (each covers <=2x2 windows)
    for (int j = 0; j < 8; j++) {
        int y, x; load_pt(ys_raw, xs_raw, is64, b * NP + tid + j * 256, y, x);
        y -= ymin; x -= xmin;
        const int n = tid + j * 256;
        const int ilo = (y > 8) ? (y - 3) / 6 : 0;
        int       ihi = y / 6;  if (ihi > nH - 1) ihi = nH - 1;
        const int jlo = (x > 8) ? (x - 3) / 6 : 0;
        int       jhi = x / 6;  if (jhi > nW - 1) jhi = nW - 1;
        for (int i = ilo; i <= ihi; i++)
            for (int jj = jlo; jj <= jhi; jj++) {
                const int slot = s_slot[i * nW + jj];
                if (slot >= 0) {
                    const int pos = atomicAdd(&s_cntA[slot], 1);
                    g_list[(b * SLOTMAX + slot) * CELLS + pos] =
                        ((y - i * 6) * TSZ + (x - jj * 6)) << 16 | n;
                }
            }
    }
    __syncthreads();
    g_cnt[b * SLOTMAX + tid]       = s_cntA[tid];
    g_cnt[b * SLOTMAX + tid + 256] = s_cntA[tid + 256];
    __threadfence();                // release this thread's stores
    __syncthreads();
    if (tid == 0) atomicAdd(&g_ready, 1);
}

// ---------------------------------------------------------------------------
// fused kernel: grid = K * NCHUNK, 256 threads.
// ---------------------------------------------------------------------------
__global__ __launch_bounds__(256, 8) void fused_kernel(const float* __restrict__ features,
                                                       const void* __restrict__ ys,
                                                       const void* __restrict__ xs,
                                                       float* __restrict__ out,
                                                       int ns_count, int head)
{
    const int tid = threadIdx.x;

    if (blockIdx.x < NB) do_setup(blockIdx.x, ys, xs);

    // wait for all 4 setup arrivals
    if (tid == 0) {
        while (atomicAdd(&g_ready, 0) < NB) __nanosleep(128);
        __threadfence();
    }
    __syncthreads();

    // ---- tiles work ----
    const int s     = blockIdx.x >> 3;          // tile
    const int chunk = blockIdx.x & (NCHUNK - 1);

    __shared__ alignas(16) float sval[CHUNK_ELEMS + 8];
    __shared__ short s_cell[CELLS], s_pn[CELLS];
    __shared__ unsigned s_bm[3];                // 81-bit occupancy bitmap
    __shared__ unsigned char s_sel4[CELLS];     // occupancy of cells c..c+3 (wrap)

    const int c0 = g_selcnt[0], c1 = g_selcnt[1], c2 = g_selcnt[2];
    int b, local = s;
    if (s < c0)                { b = 0; }
    else if (s < c0 + c1)      { b = 1; local = s - c0; }
    else if (s < c0 + c1 + c2) { b = 2; local = s - c0 - c1; }
    else                       { b = 3; local = s - c0 - c1 - c2; }
    const int cnt = g_cnt[b * SLOTMAX + local];

    if (tid < 3) s_bm[tid] = 0;
    __syncthreads();
    if (tid < cnt) {
        const int e = g_list[(b * SLOTMAX + local) * CELLS + tid];
        const int cell = e >> 16;
        s_cell[tid] = (short)cell;
        s_pn[tid]   = (short)(e & 0xffff);
        atomicOr(&s_bm[cell >> 5], 1u << (cell & 31));
    }
    if (tid == 0 && ns_count > 0 && chunk == 0) out[s] = (float)b;   // f_ns
    __syncthreads();

    const int ofs = (4 - head) & 3;             // (ofs+head) % 4 == 0
    const float* __restrict__ fb = features + (size_t)b * (NP * NC) + chunk * CHUNK;

    // sel4 table + fill occupied columns (coalesced LDG, stride-81 STS)
    if (tid < CELLS) {
        unsigned sel = 0;
#pragma unroll
        for (int e = 0; e < 4; e++) {
            unsigned cq = (unsigned)tid + e; if (cq >= CELLS) cq -= CELLS;
            sel |= ((s_bm[cq >> 5] >> (cq & 31u)) & 1u) << e;
        }
        s_sel4[tid] = (unsigned char)sel;
    }
    for (int i = tid; i < cnt * CHUNK; i += 256) {
        const int p = i >> 6, c = i & (CHUNK - 1);
        sval[ofs + c * CELLS + (int)s_cell[p]] = __ldg(fb + (int)s_pn[p] * NC + c);
    }
    __syncthreads();

    // emit: predicated LDS.128 (skipped when sel==0) + integer SEL blend
    float* __restrict__ oc = out + (size_t)ns_count + (size_t)s * TILE_ELEMS
                                 + (size_t)chunk * CHUNK_ELEMS;
    const int tail = (CHUNK_ELEMS - head) & 3;

    if (tid < head) {                           // head scalars: cell == lin
        const unsigned bit = (s_bm[0] >> tid) & 1u;
        const unsigned uv = bit ? __float_as_uint(sval[ofs + tid]) : 0u;
        __stcs(oc + tid, __uint_as_float(uv));
    }

    const int nb4 = (CHUNK_ELEMS - head - tail) >> 2;
    const unsigned* __restrict__ svu = (const unsigned*)sval;
    int lin = head + tid * 4;
    unsigned cc = (unsigned)lin % 81u;          // one mod per thread

#pragma unroll 2
    for (int k = tid; k < nb4; k += 256) {
        const unsigned sel = s_sel4[cc];
        uint4 l;
        if (sel) l = *(const uint4*)(svu + ofs + lin);   // @P LDS.128
        uint4 v;
        v.x = (sel & 1u) ? l.x : 0u;
        v.y = (sel & 2u) ? l.y : 0u;
        v.z = (sel & 4u) ? l.z : 0u;
        v.w = (sel & 8u) ? l.w : 0u;
        __stcs((uint4*)(oc + lin), v);

        lin += 1024;                             // 256 threads * 4 elems
        cc += 52; if (cc >= 81u) cc -= 81u;      // 1024 mod 81 == 52
    }

    for (int k = tid; k < tail; k += 256) {
        const int l = head + (nb4 << 2) + k;
        const unsigned ce = (unsigned)l % 81u;
        const unsigned bit = (s_bm[ce >> 5] >> (ce & 31u)) & 1u;
        const unsigned uv = bit ? __float_as_uint(sval[ofs + l]) : 0u;
        __stcs(oc + l, __uint_as_float(uv));
    }

    // replay-deterministic flag reset by the last retiring block
    __syncthreads();
    if (tid == 0) {
        const int d = atomicAdd(&g_done, 1);
        if (d == (int)gridDim.x - 1) {
            g_done = 0;
            g_ready = 0;
            __threadfence();
        }
    }
}

// ---------------------------------------------------------------------------
extern "C" void kernel_launch(void* const* d_in, const int* in_sizes, int n_in,
                              void* d_out, int out_size)
{
    int fi = 0;
    for (int i = 0; i < n_in; i++)
        if (in_sizes[i] == NB * NP * NC) fi = i;
    const float* features = (const float*)d_in[fi];
    const void* ys = nullptr;
    const void* xs = nullptr;
    for (int i = 0; i < n_in; i++) {
        if (i == fi) continue;
        if (!ys) ys = d_in[i];
        else if (!xs) xs = d_in[i];
    }

    int K, ns_count;
    if (out_size % (TILE_ELEMS + 1) == 0) {
        K = out_size / (TILE_ELEMS + 1);
        ns_count = K;
    } else {
        K = out_size / TILE_ELEMS;
        ns_count = 0;
    }
    if (K <= 0) return;
    if (K > NB * SLOTMAX) K = NB * SLOTMAX;

    const int head = (4 - (ns_count & 3)) & 3;
    fused_kernel<<<K * NCHUNK, 256>>>(features, ys, xs, (float*)d_out, ns_count, head);
}

// round 15
// speedup vs baseline: 1.2905x; 1.2905x over previous
#include <cuda_runtime.h>
#include <stdint.h>

// ---------------------------------------------------------------------------
// TiledFeaturesMap: B=4, N=2048, C=512, FS=1, T_SZ=9, T_STEP=6, T_CUT=2
// Output: float32 [ f_ns (K) | f_tiles (K*512*81) ], K = out_size/41473.
// tiles_kernel: per (tile, 64-ch chunk) block; fill occupied columns in smem,
// emit branch-free: sel4 byte table + PREDICATED LDS.128 + integer SEL blend.
// ---------------------------------------------------------------------------

#define NB 4
#define NP 2048
#define NC 512
#define TSZ 9
#define CELLS 81
#define TILE_ELEMS 41472
#define SLOTMAX 512
#define CHUNK 64                        // channels per block
#define NCHUNK (NC / CHUNK)             // 8
#define CHUNK_ELEMS (CHUNK * CELLS)     // 5184

__device__ int g_selcnt[NB];
__device__ int g_cnt[NB * SLOTMAX];
__device__ int g_list[NB * SLOTMAX * CELLS];   // (cell<<16)|n

// ---------------------------------------------------------------------------
// setup: 4 blocks (one per batch) x 512 threads.
// ---------------------------------------------------------------------------
__global__ __launch_bounds__(512) void setup_kernel(const void* __restrict__ ys_raw,
                                                    const void* __restrict__ xs_raw)
{
    const int b = blockIdx.x;
    const int tid = threadIdx.x;

    __shared__ int s_bad, s_ymin, s_ymax, s_xmin, s_xmax;
    __shared__ unsigned char s_mask[512];
    __shared__ short s_slot[512];
    __shared__ int s_cnt[512];
    __shared__ int s_ws[16];
    __shared__ int s_nH, s_nW, s_T;

    if (tid == 0) { s_bad = 0; s_ymin = 1 << 30; s_ymax = -1; s_xmin = 1 << 30; s_xmax = -1; }
    s_mask[tid] = 0;
    s_cnt[tid] = 0;
    __syncthreads();

    // dtype detect (int64 LE: odd 32-bit words all 0)
    {
        const int* yw = (const int*)ys_raw;
        const int* xw = (const int*)xs_raw;
        int bad = 0;
        for (int i = b * 2 * NP + 1 + 2 * tid; i < (b + 1) * 2 * NP; i += 1024)
            bad |= yw[i] | xw[i];
        bad = __reduce_or_sync(0xffffffffu, bad);
        if ((tid & 31) == 0 && bad) atomicOr(&s_bad, 1);
    }
    __syncthreads();
    const bool is64 = (s_bad == 0);

    int py[4], px[4];
#pragma unroll
    for (int j = 0; j < 4; j++) {
        const int idx = b * NP + tid + j * 512;
        if (is64) {
            py[j] = (int)((const long long*)ys_raw)[idx];
            px[j] = (int)((const long long*)xs_raw)[idx];
        } else {
            py[j] = ((const int*)ys_raw)[idx];
            px[j] = ((const int*)xs_raw)[idx];
        }
    }
    {
        int ymn = py[0], ymx = py[0], xmn = px[0], xmx = px[0];
#pragma unroll
        for (int j = 1; j < 4; j++) {
            ymn = min(ymn, py[j]); ymx = max(ymx, py[j]);
            xmn = min(xmn, px[j]); xmx = max(xmx, px[j]);
        }
        ymn = __reduce_min_sync(0xffffffffu, ymn);
        ymx = __reduce_max_sync(0xffffffffu, ymx);
        xmn = __reduce_min_sync(0xffffffffu, xmn);
        xmx = __reduce_max_sync(0xffffffffu, xmx);
        if ((tid & 31) == 0) {
            atomicMin(&s_ymin, ymn); atomicMax(&s_ymax, ymx);
            atomicMin(&s_xmin, xmn); atomicMax(&s_xmax, xmx);
        }
    }
    __syncthreads();
    if (tid == 0) {
        s_nH = (s_ymax - s_ymin + 1) / 6 + 1;
        s_nW = (s_xmax - s_xmin + 1) / 6 + 1;
        s_T = s_nH * s_nW;
    }
    __syncthreads();
    const int nH = s_nH, nW = s_nW, T = s_T;
    const int ymin = s_ymin, xmin = s_xmin;

    // shift + center occupancy (r%6: 1 -> none; 0 -> tile q-1; 2..5 -> tile q)
#pragma unroll
    for (int j = 0; j < 4; j++) {
        const int y = py[j] - ymin, x = px[j] - xmin;
        py[j] = y; px[j] = x;
        const int qy = y / 6, ry = y - 6 * qy;
        const int qx = x / 6, rx = x - 6 * qx;
        const int cy = (ry == 1) ? -1 : ((ry == 0) ? qy - 1 : qy);
        const int cx = (rx == 1) ? -1 : ((rx == 0) ? qx - 1 : qx);
        if (cy >= 0 && cx >= 0) s_mask[cy * nW + cx] = 1;
    }
    __syncthreads();

    // inclusive scan of flags over T (<=441)
    {
        const int w = tid >> 5, lane = tid & 31;
        const int f = (tid < T) ? (int)s_mask[tid] : 0;
        int v = f;
        for (int off = 1; off < 32; off <<= 1) {
            const int t = __shfl_up_sync(0xffffffffu, v, off);
            if (lane >= off) v += t;
        }
        if (lane == 31) s_ws[w] = v;
        __syncthreads();
        if (w == 0 && lane < 16) {
            int sv = s_ws[lane];
            for (int off = 1; off < 16; off <<= 1) {
                const int t = __shfl_up_sync(0xffffu, sv, off);
                if (lane >= off) sv += t;
            }
            s_ws[lane] = sv;
        }
        __syncthreads();
        const int pre = (w > 0) ? s_ws[w - 1] : 0;
        s_slot[tid] = (short)(f ? (pre + v - 1) : -1);
        if (tid == 0) g_selcnt[b] = s_ws[15];
    }
    __syncthreads();

    // scatter points into per-slot lists (each point covers <=2x2 windows)
#pragma unroll
    for (int j = 0; j < 4; j++) {
        const int y = py[j], x = px[j];
        const int n = tid + j * 512;
        const int ilo = (y > 8) ? (y - 3) / 6 : 0;
        int       ihi = y / 6;  if (ihi > nH - 1) ihi = nH - 1;
        const int jlo = (x > 8) ? (x - 3) / 6 : 0;
        int       jhi = x / 6;  if (jhi > nW - 1) jhi = nW - 1;
        for (int i = ilo; i <= ihi; i++)
            for (int jj = jlo; jj <= jhi; jj++) {
                const int slot = s_slot[i * nW + jj];
                if (slot >= 0) {
                    const int pos = atomicAdd(&s_cnt[slot], 1);
                    g_list[(b * SLOTMAX + slot) * CELLS + pos] =
                        ((y - i * 6) * TSZ + (x - jj * 6)) << 16 | n;
                }
            }
    }
    __syncthreads();
    g_cnt[b * SLOTMAX + tid] = s_cnt[tid];
}

// ---------------------------------------------------------------------------
// tiles: one block per (tile, 64-ch chunk). Fill occupied columns only
// (coalesced LDG, conflict-free stride-81 STS). Emit: sel4 byte; LDS.128
// predicated on sel!=0 (skips ~53% of shared reads); SEL blend; STG.128.
// ---------------------------------------------------------------------------
__global__ __launch_bounds__(256, 8) void tiles_kernel(const float* __restrict__ features,
                                                       float* __restrict__ out,
                                                       int ns_count, int head)
{
    const int s     = blockIdx.x >> 3;          // tile
    const int chunk = blockIdx.x & (NCHUNK - 1);
    const int tid = threadIdx.x;

    __shared__ alignas(16) float sval[CHUNK_ELEMS + 8];
    __shared__ short s_cell[CELLS], s_pn[CELLS];
    __shared__ unsigned s_bm[3];                // 81-bit occupancy bitmap
    __shared__ unsigned char s_sel4[CELLS];     // occupancy of cells c..c+3 (wrap)

    // per-thread metadata from broadcast loads
    const int c0 = g_selcnt[0], c1 = g_selcnt[1], c2 = g_selcnt[2];
    int b, local = s;
    if (s < c0)                { b = 0; }
    else if (s < c0 + c1)      { b = 1; local = s - c0; }
    else if (s < c0 + c1 + c2) { b = 2; local = s - c0 - c1; }
    else                       { b = 3; local = s - c0 - c1 - c2; }
    const int cnt = g_cnt[b * SLOTMAX + local];

    if (tid < 3) s_bm[tid] = 0;
    __syncthreads();
    if (tid < cnt) {
        const int e = g_list[(b * SLOTMAX + local) * CELLS + tid];
        const int cell = e >> 16;
        s_cell[tid] = (short)cell;
        s_pn[tid]   = (short)(e & 0xffff);
        atomicOr(&s_bm[cell >> 5], 1u << (cell & 31));
    }
    if (tid == 0 && ns_count > 0 && chunk == 0) out[s] = (float)b;   // f_ns
    __syncthreads();

    const int ofs = (4 - head) & 3;             // (ofs+head) % 4 == 0
    const float* __restrict__ fb = features + (size_t)b * (NP * NC) + chunk * CHUNK;

    // build sel4 table (tid<81) while filling occupied columns
    if (tid < CELLS) {
        unsigned sel = 0;
#pragma unroll
        for (int e = 0; e < 4; e++) {
            unsigned cq = (unsigned)tid + e; if (cq >= CELLS) cq -= CELLS;
            sel |= ((s_bm[cq >> 5] >> (cq & 31u)) & 1u) << e;
        }
        s_sel4[tid] = (unsigned char)sel;
    }
    // fill: coalesced LDG rows; STS stride-81 words (81 odd -> conflict-free)
    for (int i = tid; i < cnt * CHUNK; i += 256) {
        const int p = i >> 6, c = i & (CHUNK - 1);
        sval[ofs + c * CELLS + (int)s_cell[p]] = __ldg(fb + (int)s_pn[p] * NC + c);
    }
    __syncthreads();

    // emit
    float* __restrict__ oc = out + (size_t)ns_count + (size_t)s * TILE_ELEMS
                                 + (size_t)chunk * CHUNK_ELEMS;
    const int tail = (CHUNK_ELEMS - head) & 3;

    if (tid < head) {                           // head scalars: cell == lin
        const unsigned bit = (s_bm[0] >> tid) & 1u;
        const unsigned uv = bit ? __float_as_uint(sval[ofs + tid]) : 0u;
        __stcs(oc + tid, __uint_as_float(uv));
    }

    const int nb4 = (CHUNK_ELEMS - head - tail) >> 2;
    const unsigned* __restrict__ svu = (const unsigned*)sval;
    int lin = head + tid * 4;
    unsigned cc = (unsigned)lin % 81u;          // one mod per thread

#pragma unroll 4
    for (int k = tid; k < nb4; k += 256) {
        const unsigned sel = s_sel4[cc];
        uint4 l = make_uint4(0u, 0u, 0u, 0u);
        if (sel) l = *(const uint4*)(svu + ofs + lin);   // @P LDS.128
        uint4 v;
        v.x = (sel & 1u) ? l.x : 0u;
        v.y = (sel & 2u) ? l.y : 0u;
        v.z = (sel & 4u) ? l.z : 0u;
        v.w = (sel & 8u) ? l.w : 0u;
        __stcs((uint4*)(oc + lin), v);

        lin += 1024;                             // 256 threads * 4 elems
        cc += 52; if (cc >= 81u) cc -= 81u;      // 1024 mod 81 == 52
    }

    for (int k = tid; k < tail; k += 256) {
        const int l = head + (nb4 << 2) + k;
        const unsigned ce = (unsigned)l % 81u;
        const unsigned bit = (s_bm[ce >> 5] >> (ce & 31u)) & 1u;
        const unsigned uv = bit ? __float_as_uint(sval[ofs + l]) : 0u;
        __stcs(oc + l, __uint_as_float(uv));
    }
}

// ---------------------------------------------------------------------------
extern "C" void kernel_launch(void* const* d_in, const int* in_sizes, int n_in,
                              void* d_out, int out_size)
{
    int fi = 0;
    for (int i = 0; i < n_in; i++)
        if (in_sizes[i] == NB * NP * NC) fi = i;
    const float* features = (const float*)d_in[fi];
    const void* ys = nullptr;
    const void* xs = nullptr;
    for (int i = 0; i < n_in; i++) {
        if (i == fi) continue;
        if (!ys) ys = d_in[i];
        else if (!xs) xs = d_in[i];
    }

    setup_kernel<<<NB, 512>>>(ys, xs);

    int K, ns_count;
    if (out_size % (TILE_ELEMS + 1) == 0) {
        K = out_size / (TILE_ELEMS + 1);
        ns_count = K;
    } else {
        K = out_size / TILE_ELEMS;
        ns_count = 0;
    }
    if (K <= 0) return;
    if (K > NB * SLOTMAX) K = NB * SLOTMAX;

    const int head = (4 - (ns_count & 3)) & 3;
    tiles_kernel<<<K * NCHUNK, 256>>>(features, (float*)d_out, ns_count, head);
}